// round 4
// baseline (speedup 1.0000x reference)
#include <cuda_runtime.h>
#include <math_constants.h>
#include <stdint.h>

#define NTOT     18432
#define TPB      512
#define TILE     512
#define NSTRIP   12                  /* 6144 / 512 */
#define NDIAG    12
#define NUNITS   144                 /* 12 diag + 66*2 offdiag halves */
#define GRID     147                 /* 144 pairwise + 2 quantile + 1 std */
#define EPT      36                  /* NTOT / TPB */
#define NWARPS   16
#define GMAX     2048
#define SMEM_BYTES 8192              /* pairwise: 4*512 f32; quantile: 2048 f32 */

static const double NPAIRS_D = 18871296.0;  /* 6144*6143/2 */
static const double RAND_STD = 1.75;
static const double IQR_RAND = 2.45;

__device__ double   g_pair_partial[NUNITS];
__device__ double   g_sum_d, g_sumsq_d;
__device__ float    g_qv[4];
__device__ unsigned g_done = 0;

/* ---------------- helpers ---------------- */
__device__ __forceinline__ float sqrt_approx(float x) {
    float r; asm("sqrt.approx.f32 %0, %1;" : "=f"(r) : "f"(x)); return r;
}
typedef unsigned long long u64;
__device__ __forceinline__ u64 addx2(u64 a, u64 b) {
    u64 r; asm("add.rn.f32x2 %0, %1, %2;" : "=l"(r) : "l"(a), "l"(b)); return r;
}
__device__ __forceinline__ u64 fmax2(u64 a, u64 b, u64 c) {
    u64 r; asm("fma.rn.f32x2 %0, %1, %2, %3;" : "=l"(r) : "l"(a), "l"(b), "l"(c)); return r;
}
__device__ __forceinline__ u64 pack2(float lo, float hi) {
    u64 r; asm("mov.b64 %0, {%1, %2};" : "=l"(r) : "f"(lo), "f"(hi)); return r;
}
__device__ __forceinline__ void unpack2(u64 v, float& lo, float& hi) {
    asm("mov.b64 {%0, %1}, %2;" : "=f"(lo), "=f"(hi) : "l"(v));
}
__device__ __forceinline__ unsigned fkey(float f) {
    unsigned u = __float_as_uint(f);
    return (u & 0x80000000u) ? ~u : (u | 0x80000000u);
}
__device__ __forceinline__ float funkey(unsigned u) {
    unsigned bits = (u & 0x80000000u) ? (u & 0x7fffffffu) : ~u;
    return __uint_as_float(bits);
}
/* clamped term: sqrt(clamp(sq, 0, 0.64)) */
__device__ __forceinline__ float term(float sq) {
    return sqrt_approx(fminf(fmaxf(sq, 0.0f), 0.64f));
}

__global__ void __launch_bounds__(TPB)
dp_fused_kernel(const float* __restrict__ g, float* __restrict__ out) {
    extern __shared__ unsigned char smem_raw[];
    const int bid = blockIdx.x;
    const int t   = threadIdx.x;
    const int w   = t >> 5;
    const int ln  = t & 31;

    __shared__ unsigned s_wcnt[NWARPS];
    __shared__ unsigned s_tot, s_gcnt;
    __shared__ float    s_fred[NWARPS];
    __shared__ int      s_last;

    if (bid < NUNITS) {
        /* ================= pairwise unit ================= */
        int a, b, h;
        if (bid < NDIAG) { a = b = bid; h = -1; }
        else {
            int o = bid - NDIAG;
            int tt = o >> 1; h = o & 1;
            a = 0; int rem = tt;
            while (rem >= NSTRIP - 1 - a) { rem -= NSTRIP - 1 - a; ++a; }
            b = a + 1 + rem;
        }

        float* sx = (float*)smem_raw;          /* j-strip coords + |r|^2 */
        float* sy = sx + TILE;
        float* sz = sy + TILE;
        float* sr = sz + TILE;

        const int j = b * TILE + t;
        {
            float xj = g[3 * j + 0], yj = g[3 * j + 1], zj = g[3 * j + 2];
            sx[t] = xj; sy[t] = yj; sz[t] = zj;
            sr[t] = fmaf(zj, zj, fmaf(yj, yj, xj * xj));
        }
        __syncthreads();

        const int i = a * TILE + t;
        const float xi = g[3 * i + 0];
        const float yi = g[3 * i + 1];
        const float zi = g[3 * i + 2];
        const float ri = fmaf(zi, zi, fmaf(yi, yi, xi * xi));

        const u64 ri2 = pack2(ri, ri);
        const u64 xm2 = pack2(-2.0f * xi, -2.0f * xi);
        const u64 ym2 = pack2(-2.0f * yi, -2.0f * yi);
        const u64 zm2 = pack2(-2.0f * zi, -2.0f * zi);
        const u64* px = (const u64*)sx;
        const u64* py = (const u64*)sy;
        const u64* pz = (const u64*)sz;
        const u64* pr = (const u64*)sr;

        float a0 = 0.f, a1 = 0.f, a2 = 0.f, a3 = 0.f;

        if (h < 0) {
            /* diag: jj > t. packed from jj = t+2 (rounded), scalar edge jj = t+1 if t even */
            if ((t & 1) == 0) {
                const int jj = t + 1;
                float s = ri + sr[jj];
                s = fmaf(sx[jj], -2.0f * xi, s);
                s = fmaf(sy[jj], -2.0f * yi, s);
                s = fmaf(sz[jj], -2.0f * zi, s);
                a1 += term(s);
            }
            const int m0 = (t + 2) >> 1;
            #pragma unroll 4
            for (int m = m0; m < TILE / 2; ++m) {
                u64 s = addx2(pr[m], ri2);
                s = fmax2(px[m], xm2, s);
                s = fmax2(py[m], ym2, s);
                s = fmax2(pz[m], zm2, s);
                float s0, s1; unpack2(s, s0, s1);
                a0 += term(s0);
                a2 += term(s1);
            }
        } else {
            const int m0 = h * (TILE / 4);        /* 128 packed iters per half */
            const int m1 = m0 + TILE / 4;
            #pragma unroll 4
            for (int m = m0; m < m1; m += 2) {
                {
                    u64 s = addx2(pr[m], ri2);
                    s = fmax2(px[m], xm2, s);
                    s = fmax2(py[m], ym2, s);
                    s = fmax2(pz[m], zm2, s);
                    float s0, s1; unpack2(s, s0, s1);
                    a0 += term(s0);
                    a1 += term(s1);
                }
                {
                    u64 s = addx2(pr[m + 1], ri2);
                    s = fmax2(px[m + 1], xm2, s);
                    s = fmax2(py[m + 1], ym2, s);
                    s = fmax2(pz[m + 1], zm2, s);
                    float s0, s1; unpack2(s, s0, s1);
                    a2 += term(s0);
                    a3 += term(s1);
                }
            }
        }

        float tot = (a0 + a1) + (a2 + a3);
        #pragma unroll
        for (int o = 16; o; o >>= 1)
            tot += __shfl_down_sync(0xffffffffu, tot, o);
        if (ln == 0) s_fred[w] = tot;
        __syncthreads();
        if (t == 0) {
            float r = 0.f;
            #pragma unroll
            for (int i2 = 0; i2 < NWARPS; ++i2) r += s_fred[i2];
            g_pair_partial[bid] = (double)r;
        }

    } else if (bid < NUNITS + 2) {
        /* ============ exact quantile pair (ranks k0, k0+1) ============ */
        const int qb = bid - NUNITS;
        const unsigned k0 = qb ? 13823u : 4607u;  /* q3 : q1 */
        const float gA = qb ? 0.6245f : -0.7245f;
        const float gB = qb ? 0.7245f : -0.6245f;

        float v[EPT];
        #pragma unroll
        for (int e = 0; e < EPT; ++e) v[e] = g[t + e * TPB];

        float lo = -CUDART_INF_F, hi = CUDART_INF_F;
        unsigned cL = 0, cH = NTOT;
        bool allEq = false;

        for (int it = 0; it < 48; ++it) {
            if (cH - cL <= (unsigned)GMAX) break;
            const unsigned klo = fkey(lo), khi = fkey(hi);
            if (khi - klo <= 1u) { allEq = true; break; }
            float cand;
            if (it == 0)      cand = gA;
            else if (it == 1) cand = gB;
            else if (it < 8) {
                double frac = ((double)k0 + 0.5 - (double)cL) / (double)(cH - cL);
                cand = (float)((double)lo + frac * ((double)hi - (double)lo));
            } else cand = funkey(klo + (khi - klo) / 2u);
            {
                unsigned kc = fkey(cand);
                if (!(kc > klo && kc < khi)) cand = funkey(klo + (khi - klo) / 2u);
            }
            unsigned c = 0;
            #pragma unroll
            for (int e = 0; e < EPT; ++e) c += (v[e] < cand) ? 1u : 0u;
            #pragma unroll
            for (int o = 16; o; o >>= 1) c += __shfl_down_sync(0xffffffffu, c, o);
            if (ln == 0) s_wcnt[w] = c;
            __syncthreads();
            if (t == 0) {
                unsigned totc = 0;
                #pragma unroll
                for (int i2 = 0; i2 < NWARPS; ++i2) totc += s_wcnt[i2];
                s_tot = totc;
            }
            __syncthreads();
            const unsigned ctot = s_tot;
            if (ctot <= k0) { lo = cand; cL = ctot; }
            else            { hi = cand; cH = ctot; }
        }

        const unsigned m  = cH - cL;
        const unsigned r0 = k0 - cL;
        const unsigned r1 = r0 + 1u;

        if (allEq) {
            if (t == 0) g_qv[2 * qb + 0] = lo;
            if (r1 < m) { if (t == 0) g_qv[2 * qb + 1] = lo; }
        } else {
            float* sub = (float*)smem_raw;
            if (t == 0) s_gcnt = 0;
            __syncthreads();
            #pragma unroll
            for (int e = 0; e < EPT; ++e) {
                float x = v[e];
                if (x >= lo && x < hi) {
                    unsigned p = atomicAdd(&s_gcnt, 1u);
                    if (p < (unsigned)GMAX) sub[p] = x;
                }
            }
            __syncthreads();
            const unsigned mm = s_gcnt;
            for (unsigned i2 = t; i2 < mm; i2 += TPB) {
                float x = sub[i2];
                unsigned cl = 0, ce = 0;
                for (unsigned jj = 0; jj < mm; ++jj) {
                    float y = sub[jj];
                    cl += (y < x) ? 1u : 0u;
                    ce += (y == x) ? 1u : 0u;
                }
                if (cl <= r0 && r0 < cl + ce) g_qv[2 * qb + 0] = x;
                if (r1 < mm && cl <= r1 && r1 < cl + ce) g_qv[2 * qb + 1] = x;
            }
        }
        if (r1 >= m) {
            float mn = CUDART_INF_F;
            #pragma unroll
            for (int e = 0; e < EPT; ++e)
                if (v[e] >= hi) mn = fminf(mn, v[e]);
            #pragma unroll
            for (int o = 16; o; o >>= 1)
                mn = fminf(mn, __shfl_down_sync(0xffffffffu, mn, o));
            if (ln == 0) s_fred[w] = mn;
            __syncthreads();
            if (t == 0) {
                float r = s_fred[0];
                #pragma unroll
                for (int i2 = 1; i2 < NWARPS; ++i2) r = fminf(r, s_fred[i2]);
                g_qv[2 * qb + 1] = r;
            }
        }

    } else {
        /* ============ std sums (fp64, deterministic) ============ */
        __shared__ double sds[NWARPS], sdq[NWARPS];
        double s = 0.0, s2 = 0.0;
        #pragma unroll
        for (int e = 0; e < EPT; ++e) {
            double x = (double)g[t + e * TPB];
            s += x; s2 += x * x;
        }
        #pragma unroll
        for (int o = 16; o; o >>= 1) {
            s  += __shfl_down_sync(0xffffffffu, s,  o);
            s2 += __shfl_down_sync(0xffffffffu, s2, o);
        }
        if (ln == 0) { sds[w] = s; sdq[w] = s2; }
        __syncthreads();
        if (t == 0) {
            double aa = 0.0, bb = 0.0;
            #pragma unroll
            for (int i2 = 0; i2 < NWARPS; ++i2) { aa += sds[i2]; bb += sdq[i2]; }
            g_sum_d = aa; g_sumsq_d = bb;
        }
    }

    /* ============ fused epilogue: last block combines ============ */
    __threadfence();
    __syncthreads();
    if (t == 0) {
        unsigned old = atomicAdd(&g_done, 1u);
        s_last = (old == (unsigned)(GRID - 1)) ? 1 : 0;
    }
    __syncthreads();
    if (s_last) {
        __threadfence();
        if (t < 32) {
            double s = 0.0;
            for (int i2 = t; i2 < NUNITS; i2 += 32) s += g_pair_partial[i2];
            #pragma unroll
            for (int o = 16; o; o >>= 1) s += __shfl_down_sync(0xffffffffu, s, o);
            if (t == 0) {
                double punish = 0.8 - s / NPAIRS_D;
                double var = (g_sumsq_d - g_sum_d * g_sum_d / (double)NTOT)
                             / (double)(NTOT - 1);
                double sd = sqrt(var);
                float q1 = 0.25f * g_qv[0] + 0.75f * g_qv[1];
                float q3 = 0.75f * g_qv[2] + 0.25f * g_qv[3];
                double dstd = sd - RAND_STD;
                double diqr = (double)(q3 - q1) - IQR_RAND;
                out[0] = (float)(punish + dstd * dstd + diqr * diqr);
                g_done = 0;  /* reset for next graph replay */
            }
        }
    }
}

extern "C" void kernel_launch(void* const* d_in, const int* in_sizes, int n_in,
                              void* d_out, int out_size) {
    (void)in_sizes; (void)n_in; (void)out_size;
    const float* g = (const float*)d_in[0];
    float* out = (float*)d_out;
    dp_fused_kernel<<<GRID, TPB, SMEM_BYTES>>>(g, out);
}